// round 9
// baseline (speedup 1.0000x reference)
#include <cuda_runtime.h>
#include <cuda_bf16.h>
#include <math.h>
#include <stdint.h>

#define SEQ   1024
#define EMB   2880
#define NH    64
#define NKV   8
#define HDIM  64
#define HD    4096
#define KVD   512
#define WIN   128
#define QT    8
#define NKEY  135
#define KSTR  68
#define NPAD  2944   // Wo rows padded to 23*128

// ---------------- device-global scratch ----------------
__device__ __align__(256) float g_q[SEQ*HD];
__device__ __align__(256) float g_k[SEQ*KVD];
__device__ __align__(256) float g_v[SEQ*KVD];
__device__ __align__(256) __nv_bfloat16 g_xhi[SEQ*EMB],  g_xlo[SEQ*EMB];
__device__ __align__(256) __nv_bfloat16 g_ahi[SEQ*HD],   g_alo[SEQ*HD];
__device__ __align__(256) __nv_bfloat16 g_Wqhi[HD*EMB],  g_Wqlo[HD*EMB];
__device__ __align__(256) __nv_bfloat16 g_Wkhi[KVD*EMB], g_Wklo[KVD*EMB];
__device__ __align__(256) __nv_bfloat16 g_Wvhi[KVD*EMB], g_Wvlo[KVD*EMB];
__device__ __align__(256) __nv_bfloat16 g_Wohi[NPAD*HD], g_Wolo[NPAD*HD];

// ---------------- helpers ----------------
__device__ __forceinline__ uint32_t smem_u32(const void* p) {
    uint32_t a;
    asm("{ .reg .u64 t; cvta.to.shared.u64 t, %1; cvt.u32.u64 %0, t; }"
        : "=r"(a) : "l"(p));
    return a;
}

#define LDSM4(d, addr) \
    asm volatile("ldmatrix.sync.aligned.m8n8.x4.shared.b16 {%0,%1,%2,%3}, [%4];" \
        : "=r"((d)[0]), "=r"((d)[1]), "=r"((d)[2]), "=r"((d)[3]) : "r"(addr))

#define MMA16816(d, a, b0, b1) \
    asm volatile("mma.sync.aligned.m16n8k16.row.col.f32.bf16.bf16.f32 " \
        "{%0,%1,%2,%3}, {%4,%5,%6,%7}, {%8,%9}, {%0,%1,%2,%3};" \
        : "+f"((d)[0]), "+f"((d)[1]), "+f"((d)[2]), "+f"((d)[3]) \
        : "r"((a)[0]), "r"((a)[1]), "r"((a)[2]), "r"((a)[3]), "r"(b0), "r"(b1))

#define CP16(dst, src) \
    asm volatile("cp.async.cg.shared.global [%0], [%1], 16;" \
        :: "r"(dst), "l"((const void*)(src)) : "memory")
#define CP_COMMIT() asm volatile("cp.async.commit_group;" ::: "memory")
#define CP_WAIT1()  asm volatile("cp.async.wait_group 1;" ::: "memory")

// ---------------- split pre-pass: fp32 -> bf16 hi + bf16 lo ----------------
__global__ void split_kernel(const float* __restrict__ src,
                             __nv_bfloat16* __restrict__ hi,
                             __nv_bfloat16* __restrict__ lo,
                             int n_src, int n_tot) {
    int i = (blockIdx.x * blockDim.x + threadIdx.x) * 4;
    if (i >= n_tot) return;
    float4 v = (i < n_src) ? *(const float4*)(src + i)
                           : make_float4(0.f, 0.f, 0.f, 0.f);
    __nv_bfloat162 h01 = __floats2bfloat162_rn(v.x, v.y);
    __nv_bfloat162 h23 = __floats2bfloat162_rn(v.z, v.w);
    __nv_bfloat162 l01 = __floats2bfloat162_rn(v.x - __bfloat162float(h01.x),
                                               v.y - __bfloat162float(h01.y));
    __nv_bfloat162 l23 = __floats2bfloat162_rn(v.z - __bfloat162float(h23.x),
                                               v.w - __bfloat162float(h23.y));
    *(uint2*)(hi + i) = make_uint2(*(uint32_t*)&h01, *(uint32_t*)&h23);
    *(uint2*)(lo + i) = make_uint2(*(uint32_t*)&l01, *(uint32_t*)&l23);
}

// ---------------- split-bf16 HMMA GEMM ----------------
// C[128 x nvalid] = A[128,K] @ B[128,K]^T + bias. 256 threads, 8 warps,
// warp tile 64x32, BK=32, 3 cp.async stages, 1 syncthreads per K-step.
// MMA schedule: 3 independent passes (AhBh, AlBh, AhBl), 16 independent
// accumulators per pass -> no RAW chains between adjacent HMMAs.
#define GKC 32
#define ASTR 40                         // bf16 per smem row (32 + 8 pad)
#define REG_BYTES (128*ASTR*2)          // 10240
#define STAGE_BYTES (4*REG_BYTES)       // 40960 (Ahi Alo Bhi Blo)
#define GSMEM (3*STAGE_BYTES + 512)     // 123392

__device__ __forceinline__ void gemm_core(
        const __nv_bfloat16* __restrict__ Ahi, const __nv_bfloat16* __restrict__ Alo, int lda,
        const __nv_bfloat16* __restrict__ Bhi, const __nv_bfloat16* __restrict__ Blo, int ldb,
        const float* __restrict__ bias, int nvalid,
        float* __restrict__ C, int ldc, int K) {
    extern __shared__ char smem[];
    uint32_t sb = smem_u32(smem);
    float* bias_sh = (float*)(smem + 3 * STAGE_BYTES);

    int tid  = threadIdx.x;
    int lane = tid & 31;
    int w    = tid >> 5;
    int bm   = blockIdx.y * 128;
    int wm   = (w >> 2) * 64;
    int wn   = (w & 3) * 32;

    if (tid < 128) bias_sh[tid] = (tid < nvalid) ? bias[tid] : 0.0f;

    const __nv_bfloat16* pA0 = Ahi + (size_t)bm * lda;
    const __nv_bfloat16* pA1 = Alo + (size_t)bm * lda;

    // cp.async per-thread coords: 8 chunks of 16B (rows row/row+64, 64B each)
    int row = tid >> 2, c4 = tid & 3;

#define LOAD_STAGE(soff, kt) do {                                               \
    uint32_t d = sb + (soff) + (uint32_t)(row * 80 + c4 * 16);                  \
    size_t sa   = (size_t)row * lda + (kt) + c4 * 8;                            \
    size_t sa2  = sa + (size_t)64 * lda;                                        \
    size_t sbb  = (size_t)row * ldb + (kt) + c4 * 8;                            \
    size_t sbb2 = sbb + (size_t)64 * ldb;                                       \
    CP16(d,                        pA0 + sa);                                   \
    CP16(d + 5120,                 pA0 + sa2);                                  \
    CP16(d + REG_BYTES,            pA1 + sa);                                   \
    CP16(d + REG_BYTES + 5120,     pA1 + sa2);                                  \
    CP16(d + 2*REG_BYTES,          Bhi + sbb);                                  \
    CP16(d + 2*REG_BYTES + 5120,   Bhi + sbb2);                                 \
    CP16(d + 3*REG_BYTES,          Blo + sbb);                                  \
    CP16(d + 3*REG_BYTES + 5120,   Blo + sbb2);                                 \
} while (0)

    // ldmatrix per-lane offsets (bytes)
    int r = lane & 7, g = lane >> 3;
    uint32_t aoff = (uint32_t)(((wm + ((g & 1) << 3) + r) * ASTR + ((g >> 1) << 3)) * 2);
    uint32_t boff = (uint32_t)(((wn + (((g >> 1) & 1) << 3) + r) * ASTR + ((g & 1) << 3)) * 2);

    float acc[4][4][4];
#pragma unroll
    for (int i = 0; i < 4; i++)
#pragma unroll
        for (int j = 0; j < 4; j++)
#pragma unroll
            for (int q = 0; q < 4; q++) acc[i][j][q] = 0.0f;

    int NC = K / GKC;
    LOAD_STAGE(0, 0);               CP_COMMIT();
    LOAD_STAGE(STAGE_BYTES, GKC);   CP_COMMIT();

    for (int c = 0; c < NC; c++) {
        CP_WAIT1();
        __syncthreads();
        // stage c+2 -> slot (c+2)%3 (last read at iter c-1; every warp is past
        // the barrier above, so overwrite is safe). Issue BEFORE compute so the
        // LSU gets a full k-step of lead time.
        if (c + 2 < NC) LOAD_STAGE(((c + 2) % 3) * STAGE_BYTES, (c + 2) * GKC);
        CP_COMMIT();

        uint32_t buf = sb + (uint32_t)((c % 3) * STAGE_BYTES);
#pragma unroll
        for (int ks = 0; ks < 2; ks++) {
            uint32_t kb = (uint32_t)(ks * 32);
            uint32_t aH[4][4], aL[4][4], bH[2][4], bL[2][4];
#pragma unroll
            for (int nf2 = 0; nf2 < 2; nf2++) {
                uint32_t bd = buf + 2 * REG_BYTES + boff + kb + (uint32_t)(nf2 * 16 * 80);
                LDSM4(bH[nf2], bd);
                LDSM4(bL[nf2], bd + REG_BYTES);
            }
#pragma unroll
            for (int mf = 0; mf < 4; mf++) {
                uint32_t ad = buf + aoff + kb + (uint32_t)(mf * 16 * 80);
                LDSM4(aH[mf], ad);
                LDSM4(aL[mf], ad + REG_BYTES);
            }
            // pass 1: Ah * Bh  (16 independent accumulators)
#pragma unroll
            for (int mf = 0; mf < 4; mf++)
#pragma unroll
                for (int nf = 0; nf < 4; nf++)
                    MMA16816(acc[mf][nf], aH[mf],
                             bH[nf >> 1][(nf & 1) * 2], bH[nf >> 1][(nf & 1) * 2 + 1]);
            // pass 2: Al * Bh
#pragma unroll
            for (int mf = 0; mf < 4; mf++)
#pragma unroll
                for (int nf = 0; nf < 4; nf++)
                    MMA16816(acc[mf][nf], aL[mf],
                             bH[nf >> 1][(nf & 1) * 2], bH[nf >> 1][(nf & 1) * 2 + 1]);
            // pass 3: Ah * Bl
#pragma unroll
            for (int mf = 0; mf < 4; mf++)
#pragma unroll
                for (int nf = 0; nf < 4; nf++)
                    MMA16816(acc[mf][nf], aH[mf],
                             bL[nf >> 1][(nf & 1) * 2], bL[nf >> 1][(nf & 1) * 2 + 1]);
        }
    }
#undef LOAD_STAGE

    // epilogue
    int rr = lane >> 2, cc = (lane & 3) * 2;
#pragma unroll
    for (int mf = 0; mf < 4; mf++) {
        int row0 = bm + wm + mf * 16 + rr;
#pragma unroll
        for (int nf = 0; nf < 4; nf++) {
            int col = wn + nf * 8 + cc;
            if (col < nvalid) {
                float b0 = bias_sh[col], b1 = bias_sh[col + 1];
                float2 v0 = make_float2(acc[mf][nf][0] + b0, acc[mf][nf][1] + b1);
                float2 v1 = make_float2(acc[mf][nf][2] + b0, acc[mf][nf][3] + b1);
                *(float2*)(C + (size_t)row0 * ldc + col)       = v0;
                *(float2*)(C + (size_t)(row0 + 8) * ldc + col) = v1;
            }
        }
    }
}

// Fused QKV: n-tiles 0-31 -> Wq, 32-35 -> Wk, 36-39 -> Wv
__global__ void __launch_bounds__(256)
qkv_gemm(const float* __restrict__ bq, const float* __restrict__ bk,
         const float* __restrict__ bv) {
    int nt = blockIdx.x;
    const __nv_bfloat16 *Bh, *Bl; const float* bi; float* C; int ldc;
    if (nt < 32) {
        Bh = g_Wqhi + (size_t)nt * 128 * EMB; Bl = g_Wqlo + (size_t)nt * 128 * EMB;
        bi = bq + nt * 128; C = g_q + nt * 128; ldc = HD;
    } else if (nt < 36) {
        int t = nt - 32;
        Bh = g_Wkhi + (size_t)t * 128 * EMB; Bl = g_Wklo + (size_t)t * 128 * EMB;
        bi = bk + t * 128; C = g_k + t * 128; ldc = KVD;
    } else {
        int t = nt - 36;
        Bh = g_Wvhi + (size_t)t * 128 * EMB; Bl = g_Wvlo + (size_t)t * 128 * EMB;
        bi = bv + t * 128; C = g_v + t * 128; ldc = KVD;
    }
    gemm_core(g_xhi, g_xlo, EMB, Bh, Bl, EMB, bi, 128, C, ldc, EMB);
}

__global__ void __launch_bounds__(256)
oproj_gemm(const float* __restrict__ bo, float* __restrict__ out) {
    int n0 = blockIdx.x * 128;
    int nv = EMB - n0; if (nv > 128) nv = 128;
    gemm_core(g_ahi, g_alo, HD,
              g_Wohi + (size_t)n0 * HD, g_Wolo + (size_t)n0 * HD, HD,
              bo + n0, nv, out + n0, EMB, HD);
}

// ---------------- RoPE (YaRN) ----------------
__global__ void rope_kernel(const int* __restrict__ positions) {
    int s = blockIdx.x;
    int tid = threadIdx.x;
    __shared__ float csh[32], ssh[32];

    if (tid < 32) {
        float i2 = 2.0f * (float)tid;
        float pf = powf(150000.0f, i2 / 64.0f);
        double lbase = 2.0 * log(150000.0);
        double low  = 64.0 * log(4096.0 / (32.0 * 2.0 * M_PI)) / lbase;
        double high = 64.0 * log(4096.0 / (1.0  * 2.0 * M_PI)) / lbase;
        if (low  < 0.0)  low  = 0.0;
        if (high > 31.0) high = 31.0;
        float ramp = ((float)tid - (float)low) / (float)(high - low);
        ramp = fminf(fmaxf(ramp, 0.0f), 1.0f);
        float invf = (1.0f / (32.0f * pf)) * ramp + (1.0f / pf) * (1.0f - ramp);
        float mscale = 0.1f * logf(32.0f) + 1.0f;
        float ang = (float)positions[s] * invf;
        csh[tid] = cosf(ang) * mscale;
        ssh[tid] = sinf(ang) * mscale;
    }
    __syncthreads();

    for (int item = tid; item < (NH + NKV) * 32; item += blockDim.x) {
        int h = item >> 5;
        int i = item & 31;
        float* base = (h < NH) ? (g_q + (size_t)s * HD + h * HDIM)
                               : (g_k + (size_t)s * KVD + (h - NH) * HDIM);
        float x0 = base[i];
        float x1 = base[i + 32];
        base[i]      = x0 * csh[i] - x1 * ssh[i];
        base[i + 32] = x1 * csh[i] + x0 * ssh[i];
    }
}

// ---------------- Attention (writes bf16 hi/lo directly) ----------------
__global__ void attn_kernel(const float* __restrict__ sinks) {
    extern __shared__ float asmem[];
    float* k_sh = asmem;
    float* v_sh = k_sh + NKEY * KSTR;
    float* q_sh = v_sh + NKEY * KSTR;
    float* p_sh = q_sh + QT * 512;

    int kvh  = blockIdx.x;
    int q0   = blockIdx.y * QT;
    int base = q0 - (WIN - 1);
    int tid  = threadIdx.x;
    int w    = tid >> 5;
    int lane = tid & 31;

    for (int i4 = tid; i4 < NKEY * 16; i4 += 256) {
        int row = i4 >> 4, d4 = i4 & 15;
        int sg = base + row;
        float4 kv = make_float4(0.f, 0.f, 0.f, 0.f);
        float4 vv = make_float4(0.f, 0.f, 0.f, 0.f);
        if (sg >= 0) {
            kv = *(const float4*)(g_k + (size_t)sg * KVD + kvh * HDIM + d4 * 4);
            vv = *(const float4*)(g_v + (size_t)sg * KVD + kvh * HDIM + d4 * 4);
        }
        *(float4*)(k_sh + row * KSTR + d4 * 4) = kv;
        *(float4*)(v_sh + row * KSTR + d4 * 4) = vv;
    }
    for (int i4 = tid; i4 < QT * 128; i4 += 256) {
        int j = i4 >> 7, d4 = i4 & 127;
        *(float4*)(q_sh + j * 512 + d4 * 4) =
            *(const float4*)(g_q + (size_t)(q0 + j) * HD + kvh * 512 + d4 * 4);
    }
    __syncthreads();

    int h = kvh * 8 + w;
    float sinkv = sinks[h];

    for (int j = 0; j < QT; j++) {
        float4 qr[16];
        const float4* q4 = (const float4*)(q_sh + j * 512 + w * 64);
#pragma unroll
        for (int d = 0; d < 16; d++) qr[d] = q4[d];

        float sc[4];
        bool  val[4];
        float mx = -INFINITY;
#pragma unroll
        for (int m = 0; m < 4; m++) {
            int off = j + lane + 32 * m;
            int sg  = base + off;
            val[m] = (sg >= 0);
            const float4* k4 = (const float4*)(k_sh + off * KSTR);
            float acc = 0.0f;
#pragma unroll
            for (int d = 0; d < 16; d++) {
                float4 kv = k4[d];
                acc += qr[d].x * kv.x + qr[d].y * kv.y
                     + qr[d].z * kv.z + qr[d].w * kv.w;
            }
            sc[m] = acc * 0.125f;
            if (val[m]) mx = fmaxf(mx, sc[m]);
        }
#pragma unroll
        for (int o = 16; o; o >>= 1) mx = fmaxf(mx, __shfl_xor_sync(0xFFFFFFFFu, mx, o));
        mx = fmaxf(mx, sinkv);

        float lsum = 0.0f;
        float p[4];
#pragma unroll
        for (int m = 0; m < 4; m++) {
            p[m] = val[m] ? __expf(sc[m] - mx) : 0.0f;
            lsum += p[m];
        }
#pragma unroll
        for (int o = 16; o; o >>= 1) lsum += __shfl_xor_sync(0xFFFFFFFFu, lsum, o);
        float inv = 1.0f / (lsum + __expf(sinkv - mx));

#pragma unroll
        for (int m = 0; m < 4; m++)
            p_sh[w * WIN + lane + 32 * m] = p[m] * inv;
        __syncwarp();

        float o0 = 0.0f, o1 = 0.0f;
        const float* vb = v_sh + j * KSTR;
        const float* pw = p_sh + w * WIN;
#pragma unroll 8
        for (int t = 0; t < WIN; t++) {
            float pp = pw[t];
            o0 += pp * vb[t * KSTR + lane];
            o1 += pp * vb[t * KSTR + lane + 32];
        }
        size_t ob = (size_t)(q0 + j) * HD + (size_t)h * HDIM;
        __nv_bfloat16 h0 = __float2bfloat16(o0);
        __nv_bfloat16 h1 = __float2bfloat16(o1);
        g_ahi[ob + lane]      = h0;
        g_ahi[ob + lane + 32] = h1;
        g_alo[ob + lane]      = __float2bfloat16(o0 - __bfloat162float(h0));
        g_alo[ob + lane + 32] = __float2bfloat16(o1 - __bfloat162float(h1));
        __syncwarp();
    }
}

// ---------------- Launch ----------------
extern "C" void kernel_launch(void* const* d_in, const int* in_sizes, int n_in,
                              void* d_out, int out_size) {
    (void)in_sizes; (void)n_in; (void)out_size;
    const float* x     = (const float*)d_in[0];
    const int*   pos   = (const int*)  d_in[1];
    const float* Wq    = (const float*)d_in[2];
    const float* bq    = (const float*)d_in[3];
    const float* Wk    = (const float*)d_in[4];
    const float* bk    = (const float*)d_in[5];
    const float* Wv    = (const float*)d_in[6];
    const float* bv    = (const float*)d_in[7];
    const float* Wo    = (const float*)d_in[8];
    const float* bo    = (const float*)d_in[9];
    const float* sinks = (const float*)d_in[10];
    float* out = (float*)d_out;

    __nv_bfloat16 *xhi, *xlo, *wqh, *wql, *wkh, *wkl, *wvh, *wvl, *woh, *wol;
    cudaGetSymbolAddress((void**)&xhi, g_xhi);  cudaGetSymbolAddress((void**)&xlo, g_xlo);
    cudaGetSymbolAddress((void**)&wqh, g_Wqhi); cudaGetSymbolAddress((void**)&wql, g_Wqlo);
    cudaGetSymbolAddress((void**)&wkh, g_Wkhi); cudaGetSymbolAddress((void**)&wkl, g_Wklo);
    cudaGetSymbolAddress((void**)&wvh, g_Wvhi); cudaGetSymbolAddress((void**)&wvl, g_Wvlo);
    cudaGetSymbolAddress((void**)&woh, g_Wohi); cudaGetSymbolAddress((void**)&wol, g_Wolo);

    size_t asz = (size_t)(2 * NKEY * KSTR + QT * 512 + 8 * WIN) * sizeof(float);
    cudaFuncSetAttribute(qkv_gemm,   cudaFuncAttributeMaxDynamicSharedMemorySize, GSMEM);
    cudaFuncSetAttribute(oproj_gemm, cudaFuncAttributeMaxDynamicSharedMemorySize, GSMEM);
    cudaFuncSetAttribute(attn_kernel, cudaFuncAttributeMaxDynamicSharedMemorySize, (int)asz);

    auto blocks = [](int n) { return (n / 4 + 255) / 256; };
    split_kernel<<<blocks(SEQ*EMB), 256>>>(x,  xhi, xlo, SEQ*EMB,  SEQ*EMB);
    split_kernel<<<blocks(HD*EMB),  256>>>(Wq, wqh, wql, HD*EMB,   HD*EMB);
    split_kernel<<<blocks(KVD*EMB), 256>>>(Wk, wkh, wkl, KVD*EMB,  KVD*EMB);
    split_kernel<<<blocks(KVD*EMB), 256>>>(Wv, wvh, wvl, KVD*EMB,  KVD*EMB);
    split_kernel<<<blocks(NPAD*HD), 256>>>(Wo, woh, wol, EMB*HD,   NPAD*HD);

    qkv_gemm<<<dim3(40, 8), 256, GSMEM>>>(bq, bk, bv);
    rope_kernel<<<SEQ, 256>>>(pos);
    attn_kernel<<<dim3(NKV, SEQ / QT), 256, asz>>>(sinks);
    oproj_gemm<<<dim3(23, 8), 256, GSMEM>>>(bo, out);
}

// round 10
// speedup vs baseline: 1.2880x; 1.2880x over previous
#include <cuda_runtime.h>
#include <cuda_bf16.h>
#include <math.h>
#include <stdint.h>

#define SEQ   1024
#define EMB   2880
#define NH    64
#define NKV   8
#define HDIM  64
#define HD    4096
#define KVD   512
#define WIN   128
#define QT    8
#define NKEY  135
#define KSTR  68

// ---------------- device-global scratch ----------------
__device__ __align__(256) float g_q[SEQ*HD];
__device__ __align__(256) float g_k[SEQ*KVD];
__device__ __align__(256) float g_v[SEQ*KVD];
__device__ __align__(256) __nv_bfloat16 g_xhi[SEQ*EMB],  g_xlo[SEQ*EMB];
__device__ __align__(256) __nv_bfloat16 g_ahi[SEQ*HD],   g_alo[SEQ*HD];
__device__ __align__(256) __nv_bfloat16 g_Wqhi[HD*EMB],  g_Wqlo[HD*EMB];
__device__ __align__(256) __nv_bfloat16 g_Wkhi[KVD*EMB], g_Wklo[KVD*EMB];
__device__ __align__(256) __nv_bfloat16 g_Wvhi[KVD*EMB], g_Wvlo[KVD*EMB];
__device__ __align__(256) __nv_bfloat16 g_Wohi[EMB*HD],  g_Wolo[EMB*HD];

// ---------------- helpers ----------------
__device__ __forceinline__ uint32_t smem_u32(const void* p) {
    uint32_t a;
    asm("{ .reg .u64 t; cvta.to.shared.u64 t, %1; cvt.u32.u64 %0, t; }"
        : "=r"(a) : "l"(p));
    return a;
}

#define LDSM4(d, addr) \
    asm volatile("ldmatrix.sync.aligned.m8n8.x4.shared.b16 {%0,%1,%2,%3}, [%4];" \
        : "=r"((d)[0]), "=r"((d)[1]), "=r"((d)[2]), "=r"((d)[3]) : "r"(addr))

#define MMA16816(d, a, b0, b1) \
    asm volatile("mma.sync.aligned.m16n8k16.row.col.f32.bf16.bf16.f32 " \
        "{%0,%1,%2,%3}, {%4,%5,%6,%7}, {%8,%9}, {%0,%1,%2,%3};" \
        : "+f"((d)[0]), "+f"((d)[1]), "+f"((d)[2]), "+f"((d)[3]) \
        : "r"((a)[0]), "r"((a)[1]), "r"((a)[2]), "r"((a)[3]), "r"(b0), "r"(b1))

#define CP16(dst, src) \
    asm volatile("cp.async.cg.shared.global [%0], [%1], 16;" \
        :: "r"(dst), "l"((const void*)(src)) : "memory")
#define CP_COMMIT() asm volatile("cp.async.commit_group;" ::: "memory")
#define CP_WAIT0()  asm volatile("cp.async.wait_group 0;" ::: "memory")

// ---------------- split pre-pass: fp32 -> bf16 hi + bf16 lo ----------------
__global__ void split_kernel(const float* __restrict__ src,
                             __nv_bfloat16* __restrict__ hi,
                             __nv_bfloat16* __restrict__ lo, int n) {
    int i = (blockIdx.x * blockDim.x + threadIdx.x) * 4;
    if (i >= n) return;
    float4 v = *(const float4*)(src + i);
    __nv_bfloat162 h01 = __floats2bfloat162_rn(v.x, v.y);
    __nv_bfloat162 h23 = __floats2bfloat162_rn(v.z, v.w);
    __nv_bfloat162 l01 = __floats2bfloat162_rn(v.x - __bfloat162float(h01.x),
                                               v.y - __bfloat162float(h01.y));
    __nv_bfloat162 l23 = __floats2bfloat162_rn(v.z - __bfloat162float(h23.x),
                                               v.w - __bfloat162float(h23.y));
    *(uint2*)(hi + i) = make_uint2(*(uint32_t*)&h01, *(uint32_t*)&h23);
    *(uint2*)(lo + i) = make_uint2(*(uint32_t*)&l01, *(uint32_t*)&l23);
}

// ---------------- split-bf16 HMMA GEMM ----------------
// Block tile 128x64, 128 threads (4 warps, warp tile 64x32), BK=32,
// 2-stage cp.async, 3 CTAs/SM (12 warps/SM). Round-3 MMA ordering.
#define GKC 32
#define ASTR 40                    // bf16 per smem row (32 + 8 pad) = 80B
#define A_BYTES  (128*80)          // 10240 per A region
#define B_BYTES  (64*80)           // 5120 per B region
#define OFF_ALO  A_BYTES           // 10240
#define OFF_BHI  (2*A_BYTES)       // 20480
#define OFF_BLO  (2*A_BYTES + B_BYTES)   // 25600
#define STAGE_BYTES (2*A_BYTES + 2*B_BYTES)  // 30720
#define GSMEM (2*STAGE_BYTES + 256)          // 61696

__device__ __forceinline__ void gemm_core(
        const __nv_bfloat16* __restrict__ Ahi, const __nv_bfloat16* __restrict__ Alo, int lda,
        const __nv_bfloat16* __restrict__ Bhi, const __nv_bfloat16* __restrict__ Blo, int ldb,
        const float* __restrict__ bias,
        float* __restrict__ C, int ldc, int K) {
    extern __shared__ char smem[];
    uint32_t sb = smem_u32(smem);
    float* bias_sh = (float*)(smem + 2 * STAGE_BYTES);

    int tid  = threadIdx.x;
    int lane = tid & 31;
    int w    = tid >> 5;
    int bm   = blockIdx.y * 128;
    int wm   = (w >> 1) * 64;
    int wn   = (w & 1) * 32;

    if (tid < 64) bias_sh[tid] = bias[tid];

    const __nv_bfloat16* pAh = Ahi + (size_t)bm * lda;
    const __nv_bfloat16* pAl = Alo + (size_t)bm * lda;

    // cp.async: thread -> A rows {r,r+32,r+64,r+96}, B rows {r,r+32}; 16B col c4
    int rr_ = tid >> 2, cc_ = tid & 3;

#define LOAD_STAGE(soff, kt) do {                                            \
    uint32_t dA = sb + (soff) + (uint32_t)(rr_ * 80 + cc_ * 16);             \
    const __nv_bfloat16* sAh = pAh + (size_t)rr_ * lda + (kt) + cc_ * 8;     \
    const __nv_bfloat16* sAl = pAl + (size_t)rr_ * lda + (kt) + cc_ * 8;     \
    CP16(dA,             sAh);                                               \
    CP16(dA + 32*80,     sAh + (size_t)32 * lda);                            \
    CP16(dA + 64*80,     sAh + (size_t)64 * lda);                            \
    CP16(dA + 96*80,     sAh + (size_t)96 * lda);                            \
    CP16(dA + OFF_ALO,           sAl);                                       \
    CP16(dA + OFF_ALO + 32*80,   sAl + (size_t)32 * lda);                    \
    CP16(dA + OFF_ALO + 64*80,   sAl + (size_t)64 * lda);                    \
    CP16(dA + OFF_ALO + 96*80,   sAl + (size_t)96 * lda);                    \
    uint32_t dB = sb + (soff) + OFF_BHI + (uint32_t)(rr_ * 80 + cc_ * 16);   \
    const __nv_bfloat16* sBh = Bhi + (size_t)rr_ * ldb + (kt) + cc_ * 8;     \
    const __nv_bfloat16* sBl = Blo + (size_t)rr_ * ldb + (kt) + cc_ * 8;     \
    CP16(dB,             sBh);                                               \
    CP16(dB + 32*80,     sBh + (size_t)32 * ldb);                            \
    CP16(dB + B_BYTES,           sBl);                                       \
    CP16(dB + B_BYTES + 32*80,   sBl + (size_t)32 * ldb);                    \
} while (0)

    // ldmatrix per-lane offsets (bytes), relative to region base
    int r = lane & 7, g = lane >> 3;
    uint32_t aoff = (uint32_t)(((wm + ((g & 1) << 3) + r) * ASTR + ((g >> 1) << 3)) * 2);
    uint32_t boff = (uint32_t)(((wn + (((g >> 1) & 1) << 3) + r) * ASTR + ((g & 1) << 3)) * 2);

    float acc[4][4][4];
#pragma unroll
    for (int i = 0; i < 4; i++)
#pragma unroll
        for (int j = 0; j < 4; j++)
#pragma unroll
            for (int q = 0; q < 4; q++) acc[i][j][q] = 0.0f;

    int NC = K / GKC;
    LOAD_STAGE(0, 0);
    CP_COMMIT();

    for (int c = 0; c < NC; c++) {
        CP_WAIT0();
        __syncthreads();
        // prefetch next k-tile into the other buffer (overlaps compute below)
        if (c + 1 < NC) { LOAD_STAGE(((c + 1) & 1) * STAGE_BYTES, (c + 1) * GKC); }
        CP_COMMIT();

        uint32_t buf = sb + (uint32_t)((c & 1) * STAGE_BYTES);
#pragma unroll
        for (int ks = 0; ks < 2; ks++) {
            uint32_t kb = (uint32_t)(ks * 32);
            uint32_t bH[2][4], bL[2][4];
#pragma unroll
            for (int nf2 = 0; nf2 < 2; nf2++) {
                uint32_t bd = buf + OFF_BHI + boff + kb + (uint32_t)(nf2 * 16 * 80);
                LDSM4(bH[nf2], bd);
                LDSM4(bL[nf2], bd + B_BYTES);
            }
#pragma unroll
            for (int mf = 0; mf < 4; mf++) {
                uint32_t aH[4], aL[4];
                uint32_t ad = buf + aoff + kb + (uint32_t)(mf * 16 * 80);
                LDSM4(aH, ad);
                LDSM4(aL, ad + OFF_ALO);
#pragma unroll
                for (int nf = 0; nf < 4; nf++) {
                    uint32_t b0h = bH[nf >> 1][(nf & 1) * 2];
                    uint32_t b1h = bH[nf >> 1][(nf & 1) * 2 + 1];
                    uint32_t b0l = bL[nf >> 1][(nf & 1) * 2];
                    uint32_t b1l = bL[nf >> 1][(nf & 1) * 2 + 1];
                    MMA16816(acc[mf][nf], aH, b0h, b1h);
                    MMA16816(acc[mf][nf], aL, b0h, b1h);
                    MMA16816(acc[mf][nf], aH, b0l, b1l);
                }
            }
        }
        __syncthreads();
    }
#undef LOAD_STAGE

    // epilogue (all tiles full: 64 valid cols)
    int rr = lane >> 2, cc = (lane & 3) * 2;
#pragma unroll
    for (int mf = 0; mf < 4; mf++) {
        int row0 = bm + wm + mf * 16 + rr;
#pragma unroll
        for (int nf = 0; nf < 4; nf++) {
            int col = wn + nf * 8 + cc;
            float b0 = bias_sh[col], b1 = bias_sh[col + 1];
            float2 v0 = make_float2(acc[mf][nf][0] + b0, acc[mf][nf][1] + b1);
            float2 v1 = make_float2(acc[mf][nf][2] + b0, acc[mf][nf][3] + b1);
            *(float2*)(C + (size_t)row0 * ldc + col)       = v0;
            *(float2*)(C + (size_t)(row0 + 8) * ldc + col) = v1;
        }
    }
}

// Fused QKV: 80 n-tiles of 64: 0-63 Wq, 64-71 Wk, 72-79 Wv
__global__ void __launch_bounds__(128, 3)
qkv_gemm(const float* __restrict__ bq, const float* __restrict__ bk,
         const float* __restrict__ bv) {
    int nt = blockIdx.x;
    const __nv_bfloat16 *Bh, *Bl; const float* bi; float* C; int ldc;
    if (nt < 64) {
        Bh = g_Wqhi + (size_t)nt * 64 * EMB; Bl = g_Wqlo + (size_t)nt * 64 * EMB;
        bi = bq + nt * 64; C = g_q + nt * 64; ldc = HD;
    } else if (nt < 72) {
        int t = nt - 64;
        Bh = g_Wkhi + (size_t)t * 64 * EMB; Bl = g_Wklo + (size_t)t * 64 * EMB;
        bi = bk + t * 64; C = g_k + t * 64; ldc = KVD;
    } else {
        int t = nt - 72;
        Bh = g_Wvhi + (size_t)t * 64 * EMB; Bl = g_Wvlo + (size_t)t * 64 * EMB;
        bi = bv + t * 64; C = g_v + t * 64; ldc = KVD;
    }
    gemm_core(g_xhi, g_xlo, EMB, Bh, Bl, EMB, bi, C, ldc, EMB);
}

// O projection: 45 n-tiles of 64 (2880 = 45*64, exact)
__global__ void __launch_bounds__(128, 3)
oproj_gemm(const float* __restrict__ bo, float* __restrict__ out) {
    int n0 = blockIdx.x * 64;
    gemm_core(g_ahi, g_alo, HD,
              g_Wohi + (size_t)n0 * HD, g_Wolo + (size_t)n0 * HD, HD,
              bo + n0, out + n0, EMB, HD);
}

// ---------------- RoPE (YaRN) ----------------
__global__ void rope_kernel(const int* __restrict__ positions) {
    int s = blockIdx.x;
    int tid = threadIdx.x;
    __shared__ float csh[32], ssh[32];

    if (tid < 32) {
        float i2 = 2.0f * (float)tid;
        float pf = powf(150000.0f, i2 / 64.0f);
        double lbase = 2.0 * log(150000.0);
        double low  = 64.0 * log(4096.0 / (32.0 * 2.0 * M_PI)) / lbase;
        double high = 64.0 * log(4096.0 / (1.0  * 2.0 * M_PI)) / lbase;
        if (low  < 0.0)  low  = 0.0;
        if (high > 31.0) high = 31.0;
        float ramp = ((float)tid - (float)low) / (float)(high - low);
        ramp = fminf(fmaxf(ramp, 0.0f), 1.0f);
        float invf = (1.0f / (32.0f * pf)) * ramp + (1.0f / pf) * (1.0f - ramp);
        float mscale = 0.1f * logf(32.0f) + 1.0f;
        float ang = (float)positions[s] * invf;
        csh[tid] = cosf(ang) * mscale;
        ssh[tid] = sinf(ang) * mscale;
    }
    __syncthreads();

    for (int item = tid; item < (NH + NKV) * 32; item += blockDim.x) {
        int h = item >> 5;
        int i = item & 31;
        float* base = (h < NH) ? (g_q + (size_t)s * HD + h * HDIM)
                               : (g_k + (size_t)s * KVD + (h - NH) * HDIM);
        float x0 = base[i];
        float x1 = base[i + 32];
        base[i]      = x0 * csh[i] - x1 * ssh[i];
        base[i + 32] = x1 * csh[i] + x0 * ssh[i];
    }
}

// ---------------- Attention (writes bf16 hi/lo directly) ----------------
__global__ void attn_kernel(const float* __restrict__ sinks) {
    extern __shared__ float asmem[];
    float* k_sh = asmem;
    float* v_sh = k_sh + NKEY * KSTR;
    float* q_sh = v_sh + NKEY * KSTR;
    float* p_sh = q_sh + QT * 512;

    int kvh  = blockIdx.x;
    int q0   = blockIdx.y * QT;
    int base = q0 - (WIN - 1);
    int tid  = threadIdx.x;
    int w    = tid >> 5;
    int lane = tid & 31;

    for (int i4 = tid; i4 < NKEY * 16; i4 += 256) {
        int row = i4 >> 4, d4 = i4 & 15;
        int sg = base + row;
        float4 kv = make_float4(0.f, 0.f, 0.f, 0.f);
        float4 vv = make_float4(0.f, 0.f, 0.f, 0.f);
        if (sg >= 0) {
            kv = *(const float4*)(g_k + (size_t)sg * KVD + kvh * HDIM + d4 * 4);
            vv = *(const float4*)(g_v + (size_t)sg * KVD + kvh * HDIM + d4 * 4);
        }
        *(float4*)(k_sh + row * KSTR + d4 * 4) = kv;
        *(float4*)(v_sh + row * KSTR + d4 * 4) = vv;
    }
    for (int i4 = tid; i4 < QT * 128; i4 += 256) {
        int j = i4 >> 7, d4 = i4 & 127;
        *(float4*)(q_sh + j * 512 + d4 * 4) =
            *(const float4*)(g_q + (size_t)(q0 + j) * HD + kvh * 512 + d4 * 4);
    }
    __syncthreads();

    int h = kvh * 8 + w;
    float sinkv = sinks[h];

    for (int j = 0; j < QT; j++) {
        float4 qr[16];
        const float4* q4 = (const float4*)(q_sh + j * 512 + w * 64);
#pragma unroll
        for (int d = 0; d < 16; d++) qr[d] = q4[d];

        float sc[4];
        bool  val[4];
        float mx = -INFINITY;
#pragma unroll
        for (int m = 0; m < 4; m++) {
            int off = j + lane + 32 * m;
            int sg  = base + off;
            val[m] = (sg >= 0);
            const float4* k4 = (const float4*)(k_sh + off * KSTR);
            float acc = 0.0f;
#pragma unroll
            for (int d = 0; d < 16; d++) {
                float4 kv = k4[d];
                acc += qr[d].x * kv.x + qr[d].y * kv.y
                     + qr[d].z * kv.z + qr[d].w * kv.w;
            }
            sc[m] = acc * 0.125f;
            if (val[m]) mx = fmaxf(mx, sc[m]);
        }
#pragma unroll
        for (int o = 16; o; o >>= 1) mx = fmaxf(mx, __shfl_xor_sync(0xFFFFFFFFu, mx, o));
        mx = fmaxf(mx, sinkv);

        float lsum = 0.0f;
        float p[4];
#pragma unroll
        for (int m = 0; m < 4; m++) {
            p[m] = val[m] ? __expf(sc[m] - mx) : 0.0f;
            lsum += p[m];
        }
#pragma unroll
        for (int o = 16; o; o >>= 1) lsum += __shfl_xor_sync(0xFFFFFFFFu, lsum, o);
        float inv = 1.0f / (lsum + __expf(sinkv - mx));

#pragma unroll
        for (int m = 0; m < 4; m++)
            p_sh[w * WIN + lane + 32 * m] = p[m] * inv;
        __syncwarp();

        float o0 = 0.0f, o1 = 0.0f;
        const float* vb = v_sh + j * KSTR;
        const float* pw = p_sh + w * WIN;
#pragma unroll 8
        for (int t = 0; t < WIN; t++) {
            float pp = pw[t];
            o0 += pp * vb[t * KSTR + lane];
            o1 += pp * vb[t * KSTR + lane + 32];
        }
        size_t ob = (size_t)(q0 + j) * HD + (size_t)h * HDIM;
        __nv_bfloat16 h0 = __float2bfloat16(o0);
        __nv_bfloat16 h1 = __float2bfloat16(o1);
        g_ahi[ob + lane]      = h0;
        g_ahi[ob + lane + 32] = h1;
        g_alo[ob + lane]      = __float2bfloat16(o0 - __bfloat162float(h0));
        g_alo[ob + lane + 32] = __float2bfloat16(o1 - __bfloat162float(h1));
        __syncwarp();
    }
}

// ---------------- Launch ----------------
extern "C" void kernel_launch(void* const* d_in, const int* in_sizes, int n_in,
                              void* d_out, int out_size) {
    (void)in_sizes; (void)n_in; (void)out_size;
    const float* x     = (const float*)d_in[0];
    const int*   pos   = (const int*)  d_in[1];
    const float* Wq    = (const float*)d_in[2];
    const float* bq    = (const float*)d_in[3];
    const float* Wk    = (const float*)d_in[4];
    const float* bk    = (const float*)d_in[5];
    const float* Wv    = (const float*)d_in[6];
    const float* bv    = (const float*)d_in[7];
    const float* Wo    = (const float*)d_in[8];
    const float* bo    = (const float*)d_in[9];
    const float* sinks = (const float*)d_in[10];
    float* out = (float*)d_out;

    __nv_bfloat16 *xhi, *xlo, *wqh, *wql, *wkh, *wkl, *wvh, *wvl, *woh, *wol;
    cudaGetSymbolAddress((void**)&xhi, g_xhi);  cudaGetSymbolAddress((void**)&xlo, g_xlo);
    cudaGetSymbolAddress((void**)&wqh, g_Wqhi); cudaGetSymbolAddress((void**)&wql, g_Wqlo);
    cudaGetSymbolAddress((void**)&wkh, g_Wkhi); cudaGetSymbolAddress((void**)&wkl, g_Wklo);
    cudaGetSymbolAddress((void**)&wvh, g_Wvhi); cudaGetSymbolAddress((void**)&wvl, g_Wvlo);
    cudaGetSymbolAddress((void**)&woh, g_Wohi); cudaGetSymbolAddress((void**)&wol, g_Wolo);

    size_t asz = (size_t)(2 * NKEY * KSTR + QT * 512 + 8 * WIN) * sizeof(float);
    cudaFuncSetAttribute(qkv_gemm,   cudaFuncAttributeMaxDynamicSharedMemorySize, GSMEM);
    cudaFuncSetAttribute(oproj_gemm, cudaFuncAttributeMaxDynamicSharedMemorySize, GSMEM);
    cudaFuncSetAttribute(attn_kernel, cudaFuncAttributeMaxDynamicSharedMemorySize, (int)asz);

    auto blocks = [](int n) { return (n / 4 + 255) / 256; };
    split_kernel<<<blocks(SEQ*EMB), 256>>>(x,  xhi, xlo, SEQ*EMB);
    split_kernel<<<blocks(HD*EMB),  256>>>(Wq, wqh, wql, HD*EMB);
    split_kernel<<<blocks(KVD*EMB), 256>>>(Wk, wkh, wkl, KVD*EMB);
    split_kernel<<<blocks(KVD*EMB), 256>>>(Wv, wvh, wvl, KVD*EMB);
    split_kernel<<<blocks(EMB*HD),  256>>>(Wo, woh, wol, EMB*HD);

    qkv_gemm<<<dim3(80, 8), 128, GSMEM>>>(bq, bk, bv);
    rope_kernel<<<SEQ, 256>>>(pos);
    attn_kernel<<<dim3(NKV, SEQ / QT), 256, asz>>>(sinks);
    oproj_gemm<<<dim3(45, 8), 128, GSMEM>>>(bo, out);
}

// round 11
// speedup vs baseline: 1.4429x; 1.1203x over previous
#include <cuda_runtime.h>
#include <cuda_bf16.h>
#include <math.h>
#include <stdint.h>

#define SEQ   1024
#define EMB   2880
#define NH    64
#define NKV   8
#define HDIM  64
#define HD    4096
#define KVD   512
#define WIN   128
#define QT    8
#define NKEY  135
#define KSTR  68

// ---------------- device-global scratch ----------------
__device__ __align__(256) float g_q[SEQ*HD];
__device__ __align__(256) float g_k[SEQ*KVD];
__device__ __align__(256) float g_v[SEQ*KVD];
__device__ __align__(256) __nv_bfloat16 g_xhi[SEQ*EMB],  g_xlo[SEQ*EMB];
__device__ __align__(256) __nv_bfloat16 g_ahi[SEQ*HD],   g_alo[SEQ*HD];
__device__ __align__(256) __nv_bfloat16 g_Wqhi[HD*EMB],  g_Wqlo[HD*EMB];
__device__ __align__(256) __nv_bfloat16 g_Wkhi[KVD*EMB], g_Wklo[KVD*EMB];
__device__ __align__(256) __nv_bfloat16 g_Wvhi[KVD*EMB], g_Wvlo[KVD*EMB];
__device__ __align__(256) __nv_bfloat16 g_Wohi[EMB*HD],  g_Wolo[EMB*HD];

// ---------------- helpers ----------------
__device__ __forceinline__ uint32_t smem_u32(const void* p) {
    uint32_t a;
    asm("{ .reg .u64 t; cvta.to.shared.u64 t, %1; cvt.u32.u64 %0, t; }"
        : "=r"(a) : "l"(p));
    return a;
}

#define SWZ(o) ((o) ^ (((o) >> 3) & 0x70))

#define LDSM4(d, addr) \
    asm volatile("ldmatrix.sync.aligned.m8n8.x4.shared.b16 {%0,%1,%2,%3}, [%4];" \
        : "=r"((d)[0]), "=r"((d)[1]), "=r"((d)[2]), "=r"((d)[3]) : "r"(addr))

#define MMA16816(d, a, b0, b1) \
    asm volatile("mma.sync.aligned.m16n8k16.row.col.f32.bf16.bf16.f32 " \
        "{%0,%1,%2,%3}, {%4,%5,%6,%7}, {%8,%9}, {%0,%1,%2,%3};" \
        : "+f"((d)[0]), "+f"((d)[1]), "+f"((d)[2]), "+f"((d)[3]) \
        : "r"((a)[0]), "r"((a)[1]), "r"((a)[2]), "r"((a)[3]), "r"(b0), "r"(b1))

#define CP16(dst, src) \
    asm volatile("cp.async.cg.shared.global [%0], [%1], 16;" \
        :: "r"(dst), "l"((const void*)(src)) : "memory")
#define CP_COMMIT() asm volatile("cp.async.commit_group;" ::: "memory")
#define CP_WAIT0()  asm volatile("cp.async.wait_group 0;" ::: "memory")

// ---------------- fused split pre-pass: fp32 -> bf16 hi + lo (all tensors) ----------------
#define N4_X   (SEQ*EMB/4)
#define N4_WQ  (HD*EMB/4)
#define N4_WKV (KVD*EMB/4)
#define N4_WO  (EMB*HD/4)
#define N4_TOT (N4_X + N4_WQ + 2*N4_WKV + N4_WO)    // 7372800

__global__ void split_all(const float* __restrict__ x,  const float* __restrict__ Wq,
                          const float* __restrict__ Wk, const float* __restrict__ Wv,
                          const float* __restrict__ Wo) {
    int t = blockIdx.x * blockDim.x + threadIdx.x;   // float4 index
    const float* src; __nv_bfloat16 *hi, *lo; int i4;
    if (t < N4_X)                       { i4 = t;                      src = x;  hi = g_xhi;  lo = g_xlo;  }
    else if (t < N4_X + N4_WQ)          { i4 = t - N4_X;               src = Wq; hi = g_Wqhi; lo = g_Wqlo; }
    else if (t < N4_X + N4_WQ + N4_WKV) { i4 = t - N4_X - N4_WQ;       src = Wk; hi = g_Wkhi; lo = g_Wklo; }
    else if (t < N4_X + N4_WQ + 2*N4_WKV) { i4 = t - N4_X - N4_WQ - N4_WKV; src = Wv; hi = g_Wvhi; lo = g_Wvlo; }
    else                                { i4 = t - N4_X - N4_WQ - 2*N4_WKV; src = Wo; hi = g_Wohi; lo = g_Wolo; }
    int i = i4 * 4;
    float4 v = *(const float4*)(src + i);
    __nv_bfloat162 h01 = __floats2bfloat162_rn(v.x, v.y);
    __nv_bfloat162 h23 = __floats2bfloat162_rn(v.z, v.w);
    __nv_bfloat162 l01 = __floats2bfloat162_rn(v.x - __bfloat162float(h01.x),
                                               v.y - __bfloat162float(h01.y));
    __nv_bfloat162 l23 = __floats2bfloat162_rn(v.z - __bfloat162float(h23.x),
                                               v.w - __bfloat162float(h23.y));
    *(uint2*)(hi + i) = make_uint2(*(uint32_t*)&h01, *(uint32_t*)&h23);
    *(uint2*)(lo + i) = make_uint2(*(uint32_t*)&l01, *(uint32_t*)&l23);
}

// ---------------- split-bf16 HMMA GEMM ----------------
// Block tile 128x64, 128 threads (4 warps, warp tile 64x32), BK=32,
// 2-stage cp.async, SW128-swizzled unpadded 64B rows -> 4 CTAs/SM.
#define GKC 32
#define A_BYTES  (128*64)          // 8192 per A region
#define B_BYTES  (64*64)           // 4096 per B region
#define OFF_ALO  A_BYTES           // 8192
#define OFF_BHI  (2*A_BYTES)       // 16384
#define OFF_BLO  (2*A_BYTES + B_BYTES)       // 20480
#define STAGE_BYTES (2*A_BYTES + 2*B_BYTES)  // 24576
#define GSMEM (2*STAGE_BYTES + 256)          // 49408

__device__ __forceinline__ void gemm_core(
        const __nv_bfloat16* __restrict__ Ahi, const __nv_bfloat16* __restrict__ Alo, int lda,
        const __nv_bfloat16* __restrict__ Bhi, const __nv_bfloat16* __restrict__ Blo, int ldb,
        const float* __restrict__ bias,
        float* __restrict__ C, int ldc, int K) {
    extern __shared__ char smem[];
    uint32_t sb = smem_u32(smem);
    float* bias_sh = (float*)(smem + 2 * STAGE_BYTES);

    int tid  = threadIdx.x;
    int lane = tid & 31;
    int w    = tid >> 5;
    int bm   = blockIdx.y * 128;
    int wm   = (w >> 1) * 64;
    int wn   = (w & 1) * 32;

    if (tid < 64) bias_sh[tid] = bias[tid];

    const __nv_bfloat16* pAh = Ahi + (size_t)bm * lda;
    const __nv_bfloat16* pAl = Alo + (size_t)bm * lda;

    // cp.async: thread handles A rows {r,r+32,r+64,r+96}, B rows {r,r+32}, 16B col cc_
    int rr_ = tid >> 2, cc_ = tid & 3;
    uint32_t dA0 = (uint32_t)SWZ(rr_ * 64 + cc_ * 16);
    uint32_t dA1 = (uint32_t)SWZ((rr_ + 32) * 64 + cc_ * 16);
    uint32_t dA2 = (uint32_t)SWZ((rr_ + 64) * 64 + cc_ * 16);
    uint32_t dA3 = (uint32_t)SWZ((rr_ + 96) * 64 + cc_ * 16);
    uint32_t dB0 = dA0, dB1 = dA1;   // same pattern within B region

#define LOAD_STAGE(soff, kt) do {                                            \
    const __nv_bfloat16* sAh = pAh + (size_t)rr_ * lda + (kt) + cc_ * 8;     \
    const __nv_bfloat16* sAl = pAl + (size_t)rr_ * lda + (kt) + cc_ * 8;     \
    uint32_t base_ = sb + (soff);                                            \
    CP16(base_ + dA0,            sAh);                                       \
    CP16(base_ + dA1,            sAh + (size_t)32 * lda);                    \
    CP16(base_ + dA2,            sAh + (size_t)64 * lda);                    \
    CP16(base_ + dA3,            sAh + (size_t)96 * lda);                    \
    CP16(base_ + OFF_ALO + dA0,  sAl);                                       \
    CP16(base_ + OFF_ALO + dA1,  sAl + (size_t)32 * lda);                    \
    CP16(base_ + OFF_ALO + dA2,  sAl + (size_t)64 * lda);                    \
    CP16(base_ + OFF_ALO + dA3,  sAl + (size_t)96 * lda);                    \
    const __nv_bfloat16* sBh = Bhi + (size_t)rr_ * ldb + (kt) + cc_ * 8;     \
    const __nv_bfloat16* sBl = Blo + (size_t)rr_ * ldb + (kt) + cc_ * 8;     \
    CP16(base_ + OFF_BHI + dB0,  sBh);                                       \
    CP16(base_ + OFF_BHI + dB1,  sBh + (size_t)32 * ldb);                    \
    CP16(base_ + OFF_BLO + dB0,  sBl);                                       \
    CP16(base_ + OFF_BLO + dB1,  sBl + (size_t)32 * ldb);                    \
} while (0)

    // ldmatrix per-lane swizzled offsets (ks=0 / ks=1), mask bits invariant
    int r = lane & 7, g = lane >> 3;
    {
    }
    int a_row = wm + ((g & 1) << 3) + r;
    int a_o   = a_row * 64 + (g >> 1) * 16;
    int b_row = wn + (((g >> 1) & 1) << 3) + r;
    int b_o   = b_row * 64 + (g & 1) * 16;
    uint32_t a_sw0 = (uint32_t)SWZ(a_o);
    uint32_t a_sw1 = (uint32_t)(SWZ(a_o + 32));
    uint32_t b_sw0 = (uint32_t)SWZ(b_o);
    uint32_t b_sw1 = (uint32_t)(SWZ(b_o + 32));

    float acc[4][4][4];
#pragma unroll
    for (int i = 0; i < 4; i++)
#pragma unroll
        for (int j = 0; j < 4; j++)
#pragma unroll
            for (int q = 0; q < 4; q++) acc[i][j][q] = 0.0f;

    int NC = K / GKC;
    LOAD_STAGE(0, 0);
    CP_COMMIT();

    for (int c = 0; c < NC; c++) {
        CP_WAIT0();
        __syncthreads();
        if (c + 1 < NC) { LOAD_STAGE(((c + 1) & 1) * STAGE_BYTES, (c + 1) * GKC); }
        CP_COMMIT();

        uint32_t buf = sb + (uint32_t)((c & 1) * STAGE_BYTES);
#pragma unroll
        for (int ks = 0; ks < 2; ks++) {
            uint32_t asw = (ks == 0) ? a_sw0 : a_sw1;
            uint32_t bsw = (ks == 0) ? b_sw0 : b_sw1;
            uint32_t bH[2][4], bL[2][4];
#pragma unroll
            for (int nf2 = 0; nf2 < 2; nf2++) {
                uint32_t bd = buf + OFF_BHI + bsw + (uint32_t)(nf2 * 1024); // +16 rows
                LDSM4(bH[nf2], bd);
                LDSM4(bL[nf2], bd + B_BYTES);
            }
#pragma unroll
            for (int mf = 0; mf < 4; mf++) {
                uint32_t aH[4], aL[4];
                uint32_t ad = buf + asw + (uint32_t)(mf * 1024);            // +16 rows
                LDSM4(aH, ad);
                LDSM4(aL, ad + OFF_ALO);
#pragma unroll
                for (int nf = 0; nf < 4; nf++) {
                    uint32_t b0h = bH[nf >> 1][(nf & 1) * 2];
                    uint32_t b1h = bH[nf >> 1][(nf & 1) * 2 + 1];
                    uint32_t b0l = bL[nf >> 1][(nf & 1) * 2];
                    uint32_t b1l = bL[nf >> 1][(nf & 1) * 2 + 1];
                    MMA16816(acc[mf][nf], aH, b0h, b1h);
                    MMA16816(acc[mf][nf], aL, b0h, b1h);
                    MMA16816(acc[mf][nf], aH, b0l, b1l);
                }
            }
        }
        __syncthreads();
    }
#undef LOAD_STAGE

    // epilogue (all tiles full: 64 valid cols)
    int rr = lane >> 2, cc = (lane & 3) * 2;
#pragma unroll
    for (int mf = 0; mf < 4; mf++) {
        int row0 = bm + wm + mf * 16 + rr;
#pragma unroll
        for (int nf = 0; nf < 4; nf++) {
            int col = wn + nf * 8 + cc;
            float b0 = bias_sh[col], b1 = bias_sh[col + 1];
            float2 v0 = make_float2(acc[mf][nf][0] + b0, acc[mf][nf][1] + b1);
            float2 v1 = make_float2(acc[mf][nf][2] + b0, acc[mf][nf][3] + b1);
            *(float2*)(C + (size_t)row0 * ldc + col)       = v0;
            *(float2*)(C + (size_t)(row0 + 8) * ldc + col) = v1;
        }
    }
}

// Fused QKV: 80 n-tiles of 64: 0-63 Wq, 64-71 Wk, 72-79 Wv
__global__ void __launch_bounds__(128, 4)
qkv_gemm(const float* __restrict__ bq, const float* __restrict__ bk,
         const float* __restrict__ bv) {
    int nt = blockIdx.x;
    const __nv_bfloat16 *Bh, *Bl; const float* bi; float* C; int ldc;
    if (nt < 64) {
        Bh = g_Wqhi + (size_t)nt * 64 * EMB; Bl = g_Wqlo + (size_t)nt * 64 * EMB;
        bi = bq + nt * 64; C = g_q + nt * 64; ldc = HD;
    } else if (nt < 72) {
        int t = nt - 64;
        Bh = g_Wkhi + (size_t)t * 64 * EMB; Bl = g_Wklo + (size_t)t * 64 * EMB;
        bi = bk + t * 64; C = g_k + t * 64; ldc = KVD;
    } else {
        int t = nt - 72;
        Bh = g_Wvhi + (size_t)t * 64 * EMB; Bl = g_Wvlo + (size_t)t * 64 * EMB;
        bi = bv + t * 64; C = g_v + t * 64; ldc = KVD;
    }
    gemm_core(g_xhi, g_xlo, EMB, Bh, Bl, EMB, bi, C, ldc, EMB);
}

// O projection: 45 n-tiles of 64 (2880 = 45*64, exact)
__global__ void __launch_bounds__(128, 4)
oproj_gemm(const float* __restrict__ bo, float* __restrict__ out) {
    int n0 = blockIdx.x * 64;
    gemm_core(g_ahi, g_alo, HD,
              g_Wohi + (size_t)n0 * HD, g_Wolo + (size_t)n0 * HD, HD,
              bo + n0, out + n0, EMB, HD);
}

// ---------------- RoPE (YaRN) ----------------
__global__ void rope_kernel(const int* __restrict__ positions) {
    int s = blockIdx.x;
    int tid = threadIdx.x;
    __shared__ float csh[32], ssh[32];

    if (tid < 32) {
        float i2 = 2.0f * (float)tid;
        float pf = powf(150000.0f, i2 / 64.0f);
        double lbase = 2.0 * log(150000.0);
        double low  = 64.0 * log(4096.0 / (32.0 * 2.0 * M_PI)) / lbase;
        double high = 64.0 * log(4096.0 / (1.0  * 2.0 * M_PI)) / lbase;
        if (low  < 0.0)  low  = 0.0;
        if (high > 31.0) high = 31.0;
        float ramp = ((float)tid - (float)low) / (float)(high - low);
        ramp = fminf(fmaxf(ramp, 0.0f), 1.0f);
        float invf = (1.0f / (32.0f * pf)) * ramp + (1.0f / pf) * (1.0f - ramp);
        float mscale = 0.1f * logf(32.0f) + 1.0f;
        float ang = (float)positions[s] * invf;
        csh[tid] = cosf(ang) * mscale;
        ssh[tid] = sinf(ang) * mscale;
    }
    __syncthreads();

    for (int item = tid; item < (NH + NKV) * 32; item += blockDim.x) {
        int h = item >> 5;
        int i = item & 31;
        float* base = (h < NH) ? (g_q + (size_t)s * HD + h * HDIM)
                               : (g_k + (size_t)s * KVD + (h - NH) * HDIM);
        float x0 = base[i];
        float x1 = base[i + 32];
        base[i]      = x0 * csh[i] - x1 * ssh[i];
        base[i + 32] = x1 * csh[i] + x0 * ssh[i];
    }
}

// ---------------- Attention (writes bf16 hi/lo directly) ----------------
__global__ void attn_kernel(const float* __restrict__ sinks) {
    extern __shared__ float asmem[];
    float* k_sh = asmem;
    float* v_sh = k_sh + NKEY * KSTR;
    float* q_sh = v_sh + NKEY * KSTR;
    float* p_sh = q_sh + QT * 512;

    int kvh  = blockIdx.x;
    int q0   = blockIdx.y * QT;
    int base = q0 - (WIN - 1);
    int tid  = threadIdx.x;
    int w    = tid >> 5;
    int lane = tid & 31;

    for (int i4 = tid; i4 < NKEY * 16; i4 += 256) {
        int row = i4 >> 4, d4 = i4 & 15;
        int sg = base + row;
        float4 kv = make_float4(0.f, 0.f, 0.f, 0.f);
        float4 vv = make_float4(0.f, 0.f, 0.f, 0.f);
        if (sg >= 0) {
            kv = *(const float4*)(g_k + (size_t)sg * KVD + kvh * HDIM + d4 * 4);
            vv = *(const float4*)(g_v + (size_t)sg * KVD + kvh * HDIM + d4 * 4);
        }
        *(float4*)(k_sh + row * KSTR + d4 * 4) = kv;
        *(float4*)(v_sh + row * KSTR + d4 * 4) = vv;
    }
    for (int i4 = tid; i4 < QT * 128; i4 += 256) {
        int j = i4 >> 7, d4 = i4 & 127;
        *(float4*)(q_sh + j * 512 + d4 * 4) =
            *(const float4*)(g_q + (size_t)(q0 + j) * HD + kvh * 512 + d4 * 4);
    }
    __syncthreads();

    int h = kvh * 8 + w;
    float sinkv = sinks[h];

    for (int j = 0; j < QT; j++) {
        float4 qr[16];
        const float4* q4 = (const float4*)(q_sh + j * 512 + w * 64);
#pragma unroll
        for (int d = 0; d < 16; d++) qr[d] = q4[d];

        float sc[4];
        bool  val[4];
        float mx = -INFINITY;
#pragma unroll
        for (int m = 0; m < 4; m++) {
            int off = j + lane + 32 * m;
            int sg  = base + off;
            val[m] = (sg >= 0);
            const float4* k4 = (const float4*)(k_sh + off * KSTR);
            float acc = 0.0f;
#pragma unroll
            for (int d = 0; d < 16; d++) {
                float4 kv = k4[d];
                acc += qr[d].x * kv.x + qr[d].y * kv.y
                     + qr[d].z * kv.z + qr[d].w * kv.w;
            }
            sc[m] = acc * 0.125f;
            if (val[m]) mx = fmaxf(mx, sc[m]);
        }
#pragma unroll
        for (int o = 16; o; o >>= 1) mx = fmaxf(mx, __shfl_xor_sync(0xFFFFFFFFu, mx, o));
        mx = fmaxf(mx, sinkv);

        float lsum = 0.0f;
        float p[4];
#pragma unroll
        for (int m = 0; m < 4; m++) {
            p[m] = val[m] ? __expf(sc[m] - mx) : 0.0f;
            lsum += p[m];
        }
#pragma unroll
        for (int o = 16; o; o >>= 1) lsum += __shfl_xor_sync(0xFFFFFFFFu, lsum, o);
        float inv = 1.0f / (lsum + __expf(sinkv - mx));

#pragma unroll
        for (int m = 0; m < 4; m++)
            p_sh[w * WIN + lane + 32 * m] = p[m] * inv;
        __syncwarp();

        float o0 = 0.0f, o1 = 0.0f;
        const float* vb = v_sh + j * KSTR;
        const float* pw = p_sh + w * WIN;
#pragma unroll 8
        for (int t = 0; t < WIN; t++) {
            float pp = pw[t];
            o0 += pp * vb[t * KSTR + lane];
            o1 += pp * vb[t * KSTR + lane + 32];
        }
        size_t ob = (size_t)(q0 + j) * HD + (size_t)h * HDIM;
        __nv_bfloat16 h0 = __float2bfloat16(o0);
        __nv_bfloat16 h1 = __float2bfloat16(o1);
        g_ahi[ob + lane]      = h0;
        g_ahi[ob + lane + 32] = h1;
        g_alo[ob + lane]      = __float2bfloat16(o0 - __bfloat162float(h0));
        g_alo[ob + lane + 32] = __float2bfloat16(o1 - __bfloat162float(h1));
        __syncwarp();
    }
}

// ---------------- Launch ----------------
extern "C" void kernel_launch(void* const* d_in, const int* in_sizes, int n_in,
                              void* d_out, int out_size) {
    (void)in_sizes; (void)n_in; (void)out_size;
    const float* x     = (const float*)d_in[0];
    const int*   pos   = (const int*)  d_in[1];
    const float* Wq    = (const float*)d_in[2];
    const float* bq    = (const float*)d_in[3];
    const float* Wk    = (const float*)d_in[4];
    const float* bk    = (const float*)d_in[5];
    const float* Wv    = (const float*)d_in[6];
    const float* bv    = (const float*)d_in[7];
    const float* Wo    = (const float*)d_in[8];
    const float* bo    = (const float*)d_in[9];
    const float* sinks = (const float*)d_in[10];
    float* out = (float*)d_out;

    size_t asz = (size_t)(2 * NKEY * KSTR + QT * 512 + 8 * WIN) * sizeof(float);
    cudaFuncSetAttribute(qkv_gemm,   cudaFuncAttributeMaxDynamicSharedMemorySize, GSMEM);
    cudaFuncSetAttribute(oproj_gemm, cudaFuncAttributeMaxDynamicSharedMemorySize, GSMEM);
    cudaFuncSetAttribute(attn_kernel, cudaFuncAttributeMaxDynamicSharedMemorySize, (int)asz);

    split_all<<<N4_TOT / 256, 256>>>(x, Wq, Wk, Wv, Wo);
    qkv_gemm<<<dim3(80, 8), 128, GSMEM>>>(bq, bk, bv);
    rope_kernel<<<SEQ, 256>>>(pos);
    attn_kernel<<<dim3(NKV, SEQ / QT), 256, asz>>>(sinks);
    oproj_gemm<<<dim3(45, 8), 128, GSMEM>>>(bo, out);
}